// round 1
// baseline (speedup 1.0000x reference)
#include <cuda_runtime.h>
#include <math.h>

#define N_TOK   8192
#define DMODEL  512
#define NEXP    8
#define HID     1024
#define RHID    256
#define INDIM   4611
#define XLD     4624          // INDIM padded to multiple of 16, zero-filled
#define NROWS   (N_TOK * 2)   // top-2 gathered rows
#define LN_EPS  1e-5f

typedef unsigned long long u64;

// ------------------------- static scratch (no allocs allowed) ---------------
__device__ __align__(16) float g_x[(size_t)N_TOK * XLD];        // fused input [N, XLD]
__device__ __align__(16) float g_zres[(size_t)N_TOK * DMODEL];  // masked residual
__device__ __align__(16) float g_rh[(size_t)N_TOK * RHID];      // router hidden
__device__ float g_topw[N_TOK * 2];
__device__ int   g_topi[N_TOK * 2];
__device__ int   g_cnt[NEXP];
__device__ int   g_off[NEXP + 1];
__device__ int   g_cursor[NEXP];
__device__ int   g_rows_token[NROWS];
__device__ int   g_rows_slot[NROWS];
__device__ float g_rows_w[NROWS];
__device__ __align__(16) float g_eh[(size_t)NROWS * HID];       // expert hidden (gathered order)
__device__ __align__(16) float g_outs[(size_t)NROWS * DMODEL];  // per-slot expert outputs

// ------------------------- helpers ------------------------------------------
__device__ __forceinline__ float gelu_f(float v) {
    return 0.5f * v * (1.0f + erff(v * 0.70710678118654752440f));
}

// packed f32x2 FMA (sm_103a FFMA2) — only reachable via PTX
#define FMA2(acc, a, b) asm("fma.rn.f32x2 %0, %1, %2, %0;" : "+l"(acc) : "l"(a), "l"(b))
#define PACK2(d, f) do { unsigned _u = __float_as_uint(f); \
    asm("mov.b64 %0, {%1, %2};" : "=l"(d) : "r"(_u), "r"(_u)); } while (0)
#define UNPACK2(lo, hi, v) do { unsigned _a, _b; \
    asm("mov.b64 {%0, %1}, %2;" : "=r"(_a), "=r"(_b) : "l"(v)); \
    lo = __uint_as_float(_a); hi = __uint_as_float(_b); } while (0)

// block-wide reduce of (sum, sumsq) for 256 threads / 8 warps
__device__ __forceinline__ float2 blockReduce2(float2 v, float* sbuf) {
    int lane = threadIdx.x & 31, w = threadIdx.x >> 5;
    #pragma unroll
    for (int o = 16; o; o >>= 1) {
        v.x += __shfl_xor_sync(0xffffffffu, v.x, o);
        v.y += __shfl_xor_sync(0xffffffffu, v.y, o);
    }
    if (lane == 0) { sbuf[2 * w] = v.x; sbuf[2 * w + 1] = v.y; }
    __syncthreads();
    if (w == 0) {
        float a = (lane < 8) ? sbuf[2 * lane] : 0.f;
        float b = (lane < 8) ? sbuf[2 * lane + 1] : 0.f;
        #pragma unroll
        for (int o = 4; o; o >>= 1) {
            a += __shfl_xor_sync(0xffffffffu, a, o);
            b += __shfl_xor_sync(0xffffffffu, b, o);
        }
        if (lane == 0) { sbuf[0] = a; sbuf[1] = b; }
    }
    __syncthreads();
    float2 r = make_float2(sbuf[0], sbuf[1]);
    __syncthreads();
    return r;
}

// ------------------------- kernel 1: build fused input x --------------------
__global__ __launch_bounds__(256) void build_x_kernel(
    const float* __restrict__ z1, const float* __restrict__ z2,
    const float* __restrict__ z3, const float* __restrict__ mask,
    const float* __restrict__ ln_g, const float* __restrict__ ln_b,
    const float* __restrict__ lnp_g, const float* __restrict__ lnp_b)
{
    int n = blockIdx.x, t = threadIdx.x;
    __shared__ float a1[DMODEL], a2[DMODEL], a3[DMODEL];
    __shared__ float red[16];
    size_t zb = (size_t)n * DMODEL;
    int t1 = t + 256;

    float x1a = z1[zb + t], x1b = z1[zb + t1];
    float x2a = z2[zb + t], x2b = z2[zb + t1];
    float x3a = z3[zb + t], x3b = z3[zb + t1];
    float g0 = ln_g[t], g1 = ln_g[t1], b0 = ln_b[t], b1 = ln_b[t1];

    float2 s;
    s = blockReduce2(make_float2(x1a + x1b, x1a * x1a + x1b * x1b), red);
    float m = s.x * (1.f / DMODEL);
    float rs = rsqrtf(s.y * (1.f / DMODEL) - m * m + LN_EPS);
    float n1a = (x1a - m) * rs * g0 + b0, n1b = (x1b - m) * rs * g1 + b1;

    s = blockReduce2(make_float2(x2a + x2b, x2a * x2a + x2b * x2b), red);
    m = s.x * (1.f / DMODEL);
    rs = rsqrtf(s.y * (1.f / DMODEL) - m * m + LN_EPS);
    float n2a = (x2a - m) * rs * g0 + b0, n2b = (x2b - m) * rs * g1 + b1;

    s = blockReduce2(make_float2(x3a + x3b, x3a * x3a + x3b * x3b), red);
    m = s.x * (1.f / DMODEL);
    rs = rsqrtf(s.y * (1.f / DMODEL) - m * m + LN_EPS);
    float n3a = (x3a - m) * rs * g0 + b0, n3b = (x3b - m) * rs * g1 + b1;

    a1[t] = n1a; a1[t1] = n1b;
    a2[t] = n2a; a2[t1] = n2b;
    a3[t] = n3a; a3[t1] = n3b;

    size_t xb = (size_t)n * XLD;
    g_x[xb + t] = n1a;               g_x[xb + t1] = n1b;
    g_x[xb + DMODEL + t] = n2a;      g_x[xb + DMODEL + t1] = n2b;
    g_x[xb + 2 * DMODEL + t] = n3a;  g_x[xb + 2 * DMODEL + t1] = n3b;
    __syncthreads();

    float pg0 = lnp_g[t], pg1 = lnp_g[t1], pb0 = lnp_b[t], pb1 = lnp_b[t1];
    const float* pp[6] = {a1, a1, a2, a1, a1, a2};
    const float* qq[6] = {a2, a3, a3, a2, a3, a3};
    #pragma unroll
    for (int c = 0; c < 6; c++) {
        float u0, u1;
        if (c < 3) { u0 = pp[c][t] - qq[c][t]; u1 = pp[c][t1] - qq[c][t1]; }
        else       { u0 = pp[c][t] * qq[c][t]; u1 = pp[c][t1] * qq[c][t1]; }
        float2 sd = blockReduce2(make_float2(u0 + u1, u0 * u0 + u1 * u1), red);
        float md = sd.x * (1.f / DMODEL);
        float rsd = rsqrtf(sd.y * (1.f / DMODEL) - md * md + LN_EPS);
        size_t cb = xb + (size_t)(3 + c) * DMODEL;
        g_x[cb + t]  = (u0 - md) * rsd * pg0 + pb0;
        g_x[cb + t1] = (u1 - md) * rsd * pg1 + pb1;
    }

    if (t < 3) g_x[xb + 9 * DMODEL + t] = mask[n * 3 + t];
    for (int c = 9 * DMODEL + 3 + t; c < XLD; c += 256) g_x[xb + c] = 0.f;

    float m0 = mask[n * 3 + 0], m1m = mask[n * 3 + 1], m2m = mask[n * 3 + 2];
    float den = fmaxf(m0 + m1m + m2m, 1.f);
    g_zres[zb + t]  = (m0 * n1a + m1m * n2a + m2m * n3a) / den;
    g_zres[zb + t1] = (m0 * n1b + m1m * n2b + m2m * n3b) / den;
}

// ------------------------- GEMM inner tile (shared by all GEMMs) ------------
__device__ __forceinline__ void mma_tile16(const float (*As)[64], const float (*Bs)[64],
                                           int ty4, int tx4, u64 acc2[4][2]) {
    #pragma unroll
    for (int k = 0; k < 16; k++) {
        float4 a = *(const float4*)&As[k][ty4];
        ulonglong2 bb = *(const ulonglong2*)&Bs[k][tx4];
        u64 ax;
        PACK2(ax, a.x); FMA2(acc2[0][0], ax, bb.x); FMA2(acc2[0][1], ax, bb.y);
        PACK2(ax, a.y); FMA2(acc2[1][0], ax, bb.x); FMA2(acc2[1][1], ax, bb.y);
        PACK2(ax, a.z); FMA2(acc2[2][0], ax, bb.x); FMA2(acc2[2][1], ax, bb.y);
        PACK2(ax, a.w); FMA2(acc2[3][0], ax, bb.x); FMA2(acc2[3][1], ax, bb.y);
    }
}

// ------------------------- kernel: x @ W1 (+bias, gelu) ---------------------
// GATHER=false: router fc1 (M = N_TOK, out g_rh[*,RHID])
// GATHER=true : expert fc1 per-expert grouped rows (out g_eh, gathered order)
template <bool GATHER>
__global__ __launch_bounds__(256) void sgemm_gelu(
    const float* __restrict__ Bmat, const float* __restrict__ bias, int Mfixed)
{
    const int Bn = GATHER ? HID : RHID;
    int e = GATHER ? blockIdx.z : 0;
    int M, m_base;
    const float* Bp;
    const float* bi;
    if (GATHER) {
        m_base = g_off[e]; M = g_off[e + 1] - m_base;
        Bp = Bmat + (size_t)e * INDIM * HID;
        bi = bias + e * HID;
    } else {
        m_base = 0; M = Mfixed; Bp = Bmat; bi = bias;
    }
    int mt = blockIdx.y * 64;
    if (mt >= M) return;
    int nt = blockIdx.x * 64;

    __shared__ float As[16][64];
    __shared__ float Bs[16][64];

    int tid = threadIdx.x;
    int arow = tid >> 2, acol = (tid & 3) << 2;
    int brow = tid >> 4, bcol = (tid & 15) << 2;
    bool a_ok = (mt + arow) < M;
    int tokenRow;
    if (GATHER) tokenRow = a_ok ? g_rows_token[m_base + mt + arow] : 0;
    else        tokenRow = a_ok ? (mt + arow) : 0;
    const float* Arow = g_x + (size_t)tokenRow * XLD;

    int tx4 = (tid & 15) << 2, ty4 = (tid >> 4) << 2;
    u64 acc2[4][2];
    #pragma unroll
    for (int i = 0; i < 4; i++) { acc2[i][0] = 0ull; acc2[i][1] = 0ull; }

    for (int k0 = 0; k0 < XLD; k0 += 16) {
        float4 av = make_float4(0.f, 0.f, 0.f, 0.f);
        if (a_ok) av = *(const float4*)(Arow + k0 + acol);
        int kb = k0 + brow;
        float4 bv = make_float4(0.f, 0.f, 0.f, 0.f);
        if (kb < INDIM) bv = *(const float4*)(Bp + (size_t)kb * Bn + nt + bcol);
        As[acol + 0][arow] = av.x; As[acol + 1][arow] = av.y;
        As[acol + 2][arow] = av.z; As[acol + 3][arow] = av.w;
        *(float4*)&Bs[brow][bcol] = bv;
        __syncthreads();
        mma_tile16(As, Bs, ty4, tx4, acc2);
        __syncthreads();
    }

    float* Cbase = GATHER ? g_eh : g_rh;
    #pragma unroll
    for (int i = 0; i < 4; i++) {
        int mloc = mt + ty4 + i;
        if (mloc < M) {
            size_t roff = (size_t)(m_base + mloc) * Bn;
            float v0, v1, v2, v3;
            UNPACK2(v0, v1, acc2[i][0]);
            UNPACK2(v2, v3, acc2[i][1]);
            int nn = nt + tx4;
            Cbase[roff + nn + 0] = gelu_f(v0 + bi[nn + 0]);
            Cbase[roff + nn + 1] = gelu_f(v1 + bi[nn + 1]);
            Cbase[roff + nn + 2] = gelu_f(v2 + bi[nn + 2]);
            Cbase[roff + nn + 3] = gelu_f(v3 + bi[nn + 3]);
        }
    }
}

// ------------------------- kernel: eh @ W2 (+bias)*gate → outs --------------
__global__ __launch_bounds__(256) void sgemm_fc2(
    const float* __restrict__ e_w2, const float* __restrict__ e_b2)
{
    int e = blockIdx.z;
    int m_base = g_off[e];
    int M = g_off[e + 1] - m_base;
    int mt = blockIdx.y * 64;
    if (mt >= M) return;
    int nt = blockIdx.x * 64;

    __shared__ float As[16][64];
    __shared__ float Bs[16][64];

    int tid = threadIdx.x;
    int arow = tid >> 2, acol = (tid & 3) << 2;
    int brow = tid >> 4, bcol = (tid & 15) << 2;
    bool a_ok = (mt + arow) < M;
    int grow = a_ok ? (m_base + mt + arow) : m_base;
    const float* Arow = g_eh + (size_t)grow * HID;
    const float* Bp = e_w2 + (size_t)e * HID * DMODEL;

    int tx4 = (tid & 15) << 2, ty4 = (tid >> 4) << 2;
    u64 acc2[4][2];
    #pragma unroll
    for (int i = 0; i < 4; i++) { acc2[i][0] = 0ull; acc2[i][1] = 0ull; }

    for (int k0 = 0; k0 < HID; k0 += 16) {
        float4 av = make_float4(0.f, 0.f, 0.f, 0.f);
        if (a_ok) av = *(const float4*)(Arow + k0 + acol);
        int kb = k0 + brow;
        float4 bv = *(const float4*)(Bp + (size_t)kb * DMODEL + nt + bcol);
        As[acol + 0][arow] = av.x; As[acol + 1][arow] = av.y;
        As[acol + 2][arow] = av.z; As[acol + 3][arow] = av.w;
        *(float4*)&Bs[brow][bcol] = bv;
        __syncthreads();
        mma_tile16(As, Bs, ty4, tx4, acc2);
        __syncthreads();
    }

    #pragma unroll
    for (int i = 0; i < 4; i++) {
        int mloc = mt + ty4 + i;
        if (mloc < M) {
            int r = m_base + mloc;
            int token = g_rows_token[r];
            int slot = g_rows_slot[r];
            float w = g_rows_w[r];
            size_t ooff = ((size_t)token * 2 + slot) * DMODEL;
            float v0, v1, v2, v3;
            UNPACK2(v0, v1, acc2[i][0]);
            UNPACK2(v2, v3, acc2[i][1]);
            int nn = nt + tx4;
            const float* bb = e_b2 + (size_t)e * DMODEL;
            g_outs[ooff + nn + 0] = (v0 + bb[nn + 0]) * w;
            g_outs[ooff + nn + 1] = (v1 + bb[nn + 1]) * w;
            g_outs[ooff + nn + 2] = (v2 + bb[nn + 2]) * w;
            g_outs[ooff + nn + 3] = (v3 + bb[nn + 3]) * w;
        }
    }
}

// ------------------------- router head: logits, top-2 softmax ---------------
__global__ __launch_bounds__(256) void router_head(
    const float* __restrict__ r_w2, const float* __restrict__ r_b2,
    const float* __restrict__ log_temp)
{
    __shared__ float w2s[RHID * NEXP];
    __shared__ float b2s[NEXP];
    int t = threadIdx.x;
    for (int i = t; i < RHID * NEXP; i += 256) w2s[i] = r_w2[i];
    if (t < NEXP) b2s[t] = r_b2[t];
    __syncthreads();

    int n = blockIdx.x * 256 + t;
    const float* rhp = g_rh + (size_t)n * RHID;
    float acc[NEXP];
    #pragma unroll
    for (int e = 0; e < NEXP; e++) acc[e] = b2s[e];
    for (int k = 0; k < RHID; k++) {
        float rv = rhp[k];
        #pragma unroll
        for (int e = 0; e < NEXP; e++) acc[e] = fmaf(rv, w2s[k * NEXP + e], acc[e]);
    }
    float temp = expf(*log_temp);
    temp = fminf(fmaxf(temp, 1e-3f), 100.f);
    float inv_t = 1.f / temp;
    #pragma unroll
    for (int e = 0; e < NEXP; e++) acc[e] *= inv_t;

    int i0 = 0;
    #pragma unroll
    for (int e = 1; e < NEXP; e++) if (acc[e] > acc[i0]) i0 = e;
    int i1 = (i0 == 0) ? 1 : 0;
    #pragma unroll
    for (int e = 0; e < NEXP; e++)
        if (e != i0 && acc[e] > acc[i1]) i1 = e;

    float v0 = acc[i0], v1 = acc[i1];
    float e1 = expf(v1 - v0);
    float inv_s = 1.f / (1.f + e1);
    g_topi[n * 2 + 0] = i0; g_topw[n * 2 + 0] = inv_s;
    g_topi[n * 2 + 1] = i1; g_topw[n * 2 + 1] = e1 * inv_s;
    atomicAdd(&g_cnt[i0], 1);
    atomicAdd(&g_cnt[i1], 1);
}

// ------------------------- tiny bookkeeping kernels -------------------------
__global__ void zero_counts() {
    int t = threadIdx.x;
    if (t < NEXP) { g_cnt[t] = 0; g_cursor[t] = 0; }
}

__global__ void calc_offsets() {
    if (threadIdx.x == 0) {
        int s = 0;
        for (int e = 0; e < NEXP; e++) { g_off[e] = s; s += g_cnt[e]; }
        g_off[NEXP] = s;
    }
}

__global__ __launch_bounds__(256) void scatter_rows() {
    int n = blockIdx.x * 256 + threadIdx.x;
    if (n >= N_TOK) return;
    #pragma unroll
    for (int k = 0; k < 2; k++) {
        int e = g_topi[n * 2 + k];
        int pos = atomicAdd(&g_cursor[e], 1);
        int r = g_off[e] + pos;
        g_rows_token[r] = n;
        g_rows_slot[r] = k;
        g_rows_w[r] = g_topw[n * 2 + k];
    }
}

// ------------------------- combine + final LayerNorm ------------------------
__global__ __launch_bounds__(256) void combine_ln(
    const float* __restrict__ oln_g, const float* __restrict__ oln_b,
    float* __restrict__ out)
{
    int n = blockIdx.x, t = threadIdx.x, t1 = t + 256;
    __shared__ float red[16];
    size_t b0 = (size_t)(n * 2) * DMODEL, b1 = b0 + DMODEL, bz = (size_t)n * DMODEL;
    float v0 = g_outs[b0 + t]  + g_outs[b1 + t]  + g_zres[bz + t];
    float v1 = g_outs[b0 + t1] + g_outs[b1 + t1] + g_zres[bz + t1];
    float2 s = blockReduce2(make_float2(v0 + v1, v0 * v0 + v1 * v1), red);
    float m = s.x * (1.f / DMODEL);
    float rs = rsqrtf(s.y * (1.f / DMODEL) - m * m + LN_EPS);
    out[bz + t]  = (v0 - m) * rs * oln_g[t]  + oln_b[t];
    out[bz + t1] = (v1 - m) * rs * oln_g[t1] + oln_b[t1];
}

// ------------------------- launch --------------------------------------------
extern "C" void kernel_launch(void* const* d_in, const int* in_sizes, int n_in,
                              void* d_out, int out_size)
{
    const float* z1    = (const float*)d_in[0];
    const float* z2    = (const float*)d_in[1];
    const float* z3    = (const float*)d_in[2];
    const float* mask  = (const float*)d_in[3];
    const float* ln_g  = (const float*)d_in[4];
    const float* ln_b  = (const float*)d_in[5];
    const float* lnp_g = (const float*)d_in[6];
    const float* lnp_b = (const float*)d_in[7];
    const float* oln_g = (const float*)d_in[8];
    const float* oln_b = (const float*)d_in[9];
    const float* r_w1  = (const float*)d_in[10];
    const float* r_b1  = (const float*)d_in[11];
    const float* r_w2  = (const float*)d_in[12];
    const float* r_b2  = (const float*)d_in[13];
    const float* log_temp = (const float*)d_in[14];
    const float* e_w1  = (const float*)d_in[15];
    const float* e_b1  = (const float*)d_in[16];
    const float* e_w2  = (const float*)d_in[17];
    const float* e_b2  = (const float*)d_in[18];
    float* out = (float*)d_out;

    zero_counts<<<1, 32>>>();
    build_x_kernel<<<N_TOK, 256>>>(z1, z2, z3, mask, ln_g, ln_b, lnp_g, lnp_b);

    // router fc1: [N_TOK, XLD] @ [INDIM, RHID] → gelu → g_rh
    sgemm_gelu<false><<<dim3(RHID / 64, N_TOK / 64, 1), 256>>>(r_w1, r_b1, N_TOK);
    router_head<<<N_TOK / 256, 256>>>(r_w2, r_b2, log_temp);
    calc_offsets<<<1, 32>>>();
    scatter_rows<<<N_TOK / 256, 256>>>();

    // expert fc1 grouped: gathered rows @ e_w1[e] → gelu → g_eh
    sgemm_gelu<true><<<dim3(HID / 64, NROWS / 64, NEXP), 256>>>(e_w1, e_b1, 0);
    // expert fc2 grouped: g_eh @ e_w2[e], (+b2)*gate → g_outs
    sgemm_fc2<<<dim3(DMODEL / 64, NROWS / 64, NEXP), 256>>>(e_w2, e_b2);

    combine_ln<<<N_TOK, 256>>>(oln_g, oln_b, out);
}